// round 11
// baseline (speedup 1.0000x reference)
#include <cuda_runtime.h>
#include <cstdint>

#define BATCH 256
#define NSRC  10
#define NMC_C 16
#define LL_C  128
#define PLANE (LL_C * LL_C)          // 16384 floats per channel plane
#define TPB   256
#define NFILL 131072                 // 131072 * 256 float4 = whole output
#define NTAB  (BATCH * NMC_C)        // 4096 plane-pair table entries

// Override table, rebuilt in full by kernel A on every launch (deterministic).
// Word encoding for plane-pair (b, bin):
//   -1                      : no override points in this plane
//   [0, 16384)              : single override at in-plane offset w
//   bit30 set (w>0,>=16384) : two overrides: off1 = w & 0x3FFF, off2 = (w>>14)&0x3FFF
//   negative, != -1         : cnt = w & 0xFF overrides, offsets in g_aux[idx*10 + j]
__device__ int g_tab[NTAB];
__device__ int g_aux[NTAB * NSRC];

// ---------------------------------------------------------------------------
// Kernel A: build the override table. One thread per (batch, bin) pair.
// ---------------------------------------------------------------------------
__global__ void __launch_bounds__(TPB) table_kernel(
    const float* __restrict__ coord,
    const float* __restrict__ lows,
    const float* __restrict__ highs)
{
    int gid = blockIdx.x * TPB + threadIdx.x;
    if (gid >= NTAB) return;
    int b   = gid >> 4;
    int bin = gid & 15;

    float lo0 = lows[0], lo1 = lows[1], lo2 = lows[2];
    float hi0 = highs[0], hi1 = highs[1], hi2 = highs[2];

    int offs[NSRC];
    int cnt = 0;
#pragma unroll
    for (int s = 0; s < NSRC; s++) {
        const float* c = coord + (size_t)b * (3 * NSRC) + s * 3;
        float xg = (c[0]         - lo0) / (hi0 - lo0);
        float yg = (c[1]         - lo1) / (hi1 - lo1);
        float mg = (log10f(c[2]) - lo2) / (hi2 - lo2);

        int xi = (int)floorf(xg * (float)LL_C);
        int yi = (int)floorf(yg * (float)LL_C);
        int mi = (int)floorf(mg * (float)NMC_C);

        bool ok = ((unsigned)xi < LL_C) & ((unsigned)yi < LL_C) &
                  ((unsigned)mi < NMC_C) & (mi == bin);
        if (ok) offs[cnt++] = yi * LL_C + xi;
    }

    int w;
    if (cnt == 0)      w = -1;
    else if (cnt == 1) w = offs[0];
    else if (cnt == 2) w = (1 << 30) | (offs[1] << 14) | offs[0];
    else {
        w = (int)(0x80000000u | (unsigned)cnt);
        for (int j = 0; j < cnt; j++) g_aux[gid * NSRC + j] = offs[j];
    }
    g_tab[gid] = w;
}

// ---------------------------------------------------------------------------
// Kernel B: roofline fill (R1 geometry) with in-register override merge.
// One float4 store per thread; one broadcast table load per thread.
// ---------------------------------------------------------------------------
__device__ __forceinline__ void apply_override(float4& val, int o, int my, float ov) {
    if ((o >> 2) == my) {
        int l = o & 3;
        val.x = (l == 0) ? ov : val.x;
        val.y = (l == 1) ? ov : val.y;
        val.z = (l == 2) ? ov : val.z;
        val.w = (l == 3) ? ov : val.w;
    }
}

__global__ void __launch_bounds__(TPB) fill_patch_kernel(float4* __restrict__ out)
{
    int i     = blockIdx.x * TPB + threadIdx.x;   // float4 index, grid exact
    int plane = i >> 12;                          // 0..8191
    int tidx  = ((plane >> 5) << 4) | (plane & 15);

    int w = __ldg(&g_tab[tidx]);                  // block-uniform broadcast

    float v = (plane & 16) ? 0.0f : 1.0f;         // zeros half : ones half
    float4 val = make_float4(v, v, v, v);

    if (w != -1) {
        float ov = 1.0f - v;
        int my = i & 4095;                        // float4 index within plane
        if ((unsigned)w < 16384u) {               // single
            apply_override(val, w, my, ov);
        } else if (w > 0) {                       // double
            apply_override(val, w & 0x3FFF, my, ov);
            apply_override(val, (w >> 14) & 0x3FFF, my, ov);
        } else {                                  // escape list
            int cnt = w & 0xFF;
            const int* a = &g_aux[tidx * NSRC];
            for (int j = 0; j < cnt; j++)
                apply_override(val, __ldg(&a[j]), my, ov);
        }
    }
    out[i] = val;
}

extern "C" void kernel_launch(void* const* d_in, const int* in_sizes, int n_in,
                              void* d_out, int out_size) {
    const float* coord = (const float*)d_in[0];
    const float* lows  = (const float*)d_in[1];
    const float* highs = (const float*)d_in[2];

    table_kernel<<<NTAB / TPB, TPB>>>(coord, lows, highs);
    fill_patch_kernel<<<NFILL, TPB>>>((float4*)d_out);
}